// round 5
// baseline (speedup 1.0000x reference)
#include <cuda_runtime.h>

#define AA 512      // attention length
#define OUTS 512    // out_size
#define HH 512
#define WW 512
#define CC 3
#define NMAX 32

// scratch (allocation-free rule: device globals)
__device__ float g_px[NMAX * OUTS];
__device__ float g_py[NMAX * OUTS];

__device__ __forceinline__ float warpSum(float v) {
    #pragma unroll
    for (int o = 16; o; o >>= 1) v += __shfl_xor_sync(0xffffffffu, v, o);
    return v;
}
__device__ __forceinline__ float warpMax(float v) {
    #pragma unroll
    for (int o = 16; o; o >>= 1) v = fmaxf(v, __shfl_xor_sync(0xffffffffu, v, o));
    return v;
}

// fused block reductions for two values (512 threads), one barrier pair each
__device__ void blockSum2(float a, float b, volatile float* sbuf, float* ra, float* rb) {
    int lane = threadIdx.x & 31, w = threadIdx.x >> 5;
    a = warpSum(a); b = warpSum(b);
    if (lane == 0) { sbuf[w] = a; sbuf[32 + w] = b; }
    __syncthreads();
    if (w == 0) {
        float x = (lane < 16) ? sbuf[lane] : 0.f;
        float y = (lane < 16) ? sbuf[32 + lane] : 0.f;
        x = warpSum(x); y = warpSum(y);
        if (lane == 0) { sbuf[0] = x; sbuf[32] = y; }
    }
    __syncthreads();
    *ra = sbuf[0]; *rb = sbuf[32];
    __syncthreads();
}

__device__ void blockMax2(float a, float b, volatile float* sbuf, float* ra, float* rb) {
    int lane = threadIdx.x & 31, w = threadIdx.x >> 5;
    a = warpMax(a); b = warpMax(b);
    if (lane == 0) { sbuf[w] = a; sbuf[32 + w] = b; }
    __syncthreads();
    if (w == 0) {
        float x = (lane < 16) ? sbuf[lane] : -3.4e38f;
        float y = (lane < 16) ? sbuf[32 + lane] : -3.4e38f;
        x = warpMax(x); y = warpMax(y);
        if (lane == 0) { sbuf[0] = x; sbuf[32] = y; }
    }
    __syncthreads();
    *ra = sbuf[0]; *rb = sbuf[32];
    __syncthreads();
}

// fused inclusive block scan of two 512-value sequences -> outa[tid], outb[tid]
__device__ void blockScan2(float a, float b, float* outa, float* outb, volatile float* sbuf) {
    int lane = threadIdx.x & 31, w = threadIdx.x >> 5;
    float sa = a, sb = b;
    #pragma unroll
    for (int o = 1; o < 32; o <<= 1) {
        float ta = __shfl_up_sync(0xffffffffu, sa, o);
        float tb = __shfl_up_sync(0xffffffffu, sb, o);
        if (lane >= o) { sa += ta; sb += tb; }
    }
    if (lane == 31) { sbuf[w] = sa; sbuf[32 + w] = sb; }
    __syncthreads();
    if (w == 0 && lane < 16) {
        float wa = sbuf[lane], wb = sbuf[32 + lane];
        #pragma unroll
        for (int o = 1; o < 16; o <<= 1) {
            float ta = __shfl_up_sync(0x0000ffffu, wa, o);
            float tb = __shfl_up_sync(0x0000ffffu, wb, o);
            if (lane >= o) { wa += ta; wb += tb; }
        }
        sbuf[lane] = wa; sbuf[32 + lane] = wb;
    }
    __syncthreads();
    float offa = (w > 0) ? sbuf[w - 1] : 0.f;
    float offb = (w > 0) ? sbuf[32 + w - 1] : 0.f;
    outa[threadIdx.x] = sa + offa;
    outb[threadIdx.x] = sb + offb;
    __syncthreads();
}

__device__ __forceinline__ float inv_cdf_one(const float* c, float tk) {
    // searchsorted left: first j with c[j] >= tk.
    // Range [0,512] has size 513 -> needs exactly 10 halvings.
    int l = 0, h = AA;
    #pragma unroll
    for (int it = 0; it < 10; ++it) {
        if (l < h) {
            int m = (l + h) >> 1;
            if (c[m] < tk) l = m + 1; else h = m;
        }
    }
    int j = min(l, AA - 1);
    float cp = (j > 0) ? c[j - 1] : 0.f;
    float dens = c[j] - cp;
    float p = (float)j + (tk - cp) / fmaxf(dens, 1e-6f);
    return 2.f * p / (float)AA - 1.f;
}

__global__ void __launch_bounds__(512) prep_kernel(const float* __restrict__ attx,
                                                   const float* __restrict__ atty) {
    __shared__ float sbuf[64];
    __shared__ float cx[AA];
    __shared__ float cy[AA];
    int n = blockIdx.x;
    int t = threadIdx.x;

    float ax = attx[n * AA + t];
    float ay = atty[n * AA + t];

    float sax, say;
    blockSum2(ax, ay, sbuf, &sax, &say);
    ax = ax / sax * (float)OUTS;
    ay = ay / say * (float)OUTS;

    const float thr0 = 4.0f * (float)OUTS / (float)AA;  // DENSE*out/A
    #pragma unroll
    for (int it = 0; it < 5; ++it) {
        float mx, my;
        blockMax2(ax, ay, sbuf, &mx, &my);
        float tt = fminf(mx, my);
        if (it == 0) tt = fminf(tt, thr0);
        ax = fminf(ax, tt);
        ay = fminf(ay, tt);
        blockSum2(ax, ay, sbuf, &sax, &say);
        ax += ((float)OUTS - sax) / (float)AA;
        ay += ((float)OUTS - say) / (float)AA;
    }

    blockScan2(ax, ay, cx, cy, sbuf);

    float stepx = cx[AA - 1] / (float)OUTS;
    float stepy = cy[AA - 1] / (float)OUTS;
    float tkx = ((float)t + 0.5f) * stepx;
    float tky = ((float)t + 0.5f) * stepy;

    g_px[n * OUTS + t] = inv_cdf_one(cx, tkx);
    g_py[n * OUTS + t] = inv_cdf_one(cy, tky);
}

// direct-gather sampler: each thread computes 4 pixels of one row at stride 128
// (j = tx + k*128), so every warp-level load/store touches consecutive addresses.
// block (128,4): tx = pixel lane, ty = row within group of 4. grid (OUTS/4, N).
__global__ void __launch_bounds__(512) sample_kernel(const float* __restrict__ data,
                                                     float* __restrict__ out_s,
                                                     float2* __restrict__ out_g) {
    int tx = threadIdx.x;                 // 0..127
    int i = blockIdx.x * 4 + threadIdx.y; // output row
    int n = blockIdx.y;

    float py = __ldg(&g_py[n * OUTS + i]);
    float iy = (py + 1.f) * 0.5f * (float)(HH - 1);
    float fy = floorf(iy);
    float wy = iy - fy;
    int y0 = min(max((int)fy, 0), HH - 1);
    int y1 = min(y0 + 1, HH - 1);
    float omwy = 1.f - wy;

    float pxv[4];
    int x0[4], x1[4];
    float wx[4];
    #pragma unroll
    for (int k = 0; k < 4; ++k) {
        float px = __ldg(&g_px[n * OUTS + tx + k * 128]);
        pxv[k] = px;
        float ix = (px + 1.f) * 0.5f * (float)(WW - 1);
        float fx = floorf(ix);
        wx[k] = ix - fx;
        x0[k] = min(max((int)fx, 0), WW - 1);
        x1[k] = min(x0[k] + 1, WW - 1);
    }

    const float* img = data + (size_t)n * CC * HH * WW;

    // issue all 48 gathers, then combine
    float v00[CC][4], v01[CC][4], v10[CC][4], v11[CC][4];
    #pragma unroll
    for (int c = 0; c < CC; ++c) {
        const float* r0 = img + ((size_t)c * HH + y0) * WW;
        const float* r1 = img + ((size_t)c * HH + y1) * WW;
        #pragma unroll
        for (int k = 0; k < 4; ++k) {
            v00[c][k] = __ldg(r0 + x0[k]);
            v01[c][k] = __ldg(r0 + x1[k]);
            v10[c][k] = __ldg(r1 + x0[k]);
            v11[c][k] = __ldg(r1 + x1[k]);
        }
    }

    float* o = out_s + (((size_t)n * CC) * HH + i) * WW + tx;
    #pragma unroll
    for (int c = 0; c < CC; ++c) {
        #pragma unroll
        for (int k = 0; k < 4; ++k) {
            float omwx = 1.f - wx[k];
            float top = v00[c][k] * omwx + v01[c][k] * wx[k];
            float bot = v10[c][k] * omwx + v11[c][k] * wx[k];
            o[(size_t)c * HH * WW + k * 128] = top * omwy + bot * wy;
        }
    }

    float2* g = out_g + ((size_t)n * OUTS + i) * OUTS + tx;
    #pragma unroll
    for (int k = 0; k < 4; ++k)
        g[k * 128] = make_float2(pxv[k], py);
}

extern "C" void kernel_launch(void* const* d_in, const int* in_sizes, int n_in,
                              void* d_out, int out_size) {
    const float* data = (const float*)d_in[0];
    const float* attx = (const float*)d_in[1];
    const float* atty = (const float*)d_in[2];

    int N = in_sizes[1] / AA;   // attx is (N, 512, 1)

    float* out = (float*)d_out;
    float* out_s = out;                                        // (N, C, 512, 512)
    float2* out_g = (float2*)(out + (size_t)N * CC * HH * WW); // (N, 512, 512, 2)

    prep_kernel<<<N, 512>>>(attx, atty);
    dim3 block(128, 4);
    dim3 grid(OUTS / 4, N);
    sample_kernel<<<grid, block>>>(data, out_s, out_g);
}

// round 6
// speedup vs baseline: 1.0493x; 1.0493x over previous
#include <cuda_runtime.h>

#define AA 512      // attention length
#define OUTS 512    // out_size
#define HH 512
#define WW 512
#define CC 3
#define NMAX 32

// scratch (allocation-free rule: device globals)
__device__ float g_px[NMAX * OUTS];
__device__ float g_py[NMAX * OUTS];

__device__ __forceinline__ float warpSum(float v) {
    #pragma unroll
    for (int o = 16; o; o >>= 1) v += __shfl_xor_sync(0xffffffffu, v, o);
    return v;
}
__device__ __forceinline__ float warpMax(float v) {
    #pragma unroll
    for (int o = 16; o; o >>= 1) v = fmaxf(v, __shfl_xor_sync(0xffffffffu, v, o));
    return v;
}

// fused block reductions for two values (512 threads), one barrier pair each
__device__ void blockSum2(float a, float b, volatile float* sbuf, float* ra, float* rb) {
    int lane = threadIdx.x & 31, w = threadIdx.x >> 5;
    a = warpSum(a); b = warpSum(b);
    if (lane == 0) { sbuf[w] = a; sbuf[32 + w] = b; }
    __syncthreads();
    if (w == 0) {
        float x = (lane < 16) ? sbuf[lane] : 0.f;
        float y = (lane < 16) ? sbuf[32 + lane] : 0.f;
        x = warpSum(x); y = warpSum(y);
        if (lane == 0) { sbuf[0] = x; sbuf[32] = y; }
    }
    __syncthreads();
    *ra = sbuf[0]; *rb = sbuf[32];
    __syncthreads();
}

__device__ void blockMax2(float a, float b, volatile float* sbuf, float* ra, float* rb) {
    int lane = threadIdx.x & 31, w = threadIdx.x >> 5;
    a = warpMax(a); b = warpMax(b);
    if (lane == 0) { sbuf[w] = a; sbuf[32 + w] = b; }
    __syncthreads();
    if (w == 0) {
        float x = (lane < 16) ? sbuf[lane] : -3.4e38f;
        float y = (lane < 16) ? sbuf[32 + lane] : -3.4e38f;
        x = warpMax(x); y = warpMax(y);
        if (lane == 0) { sbuf[0] = x; sbuf[32] = y; }
    }
    __syncthreads();
    *ra = sbuf[0]; *rb = sbuf[32];
    __syncthreads();
}

// fused inclusive block scan of two 512-value sequences -> outa[tid], outb[tid]
__device__ void blockScan2(float a, float b, float* outa, float* outb, volatile float* sbuf) {
    int lane = threadIdx.x & 31, w = threadIdx.x >> 5;
    float sa = a, sb = b;
    #pragma unroll
    for (int o = 1; o < 32; o <<= 1) {
        float ta = __shfl_up_sync(0xffffffffu, sa, o);
        float tb = __shfl_up_sync(0xffffffffu, sb, o);
        if (lane >= o) { sa += ta; sb += tb; }
    }
    if (lane == 31) { sbuf[w] = sa; sbuf[32 + w] = sb; }
    __syncthreads();
    if (w == 0 && lane < 16) {
        float wa = sbuf[lane], wb = sbuf[32 + lane];
        #pragma unroll
        for (int o = 1; o < 16; o <<= 1) {
            float ta = __shfl_up_sync(0x0000ffffu, wa, o);
            float tb = __shfl_up_sync(0x0000ffffu, wb, o);
            if (lane >= o) { wa += ta; wb += tb; }
        }
        sbuf[lane] = wa; sbuf[32 + lane] = wb;
    }
    __syncthreads();
    float offa = (w > 0) ? sbuf[w - 1] : 0.f;
    float offb = (w > 0) ? sbuf[32 + w - 1] : 0.f;
    outa[threadIdx.x] = sa + offa;
    outb[threadIdx.x] = sb + offb;
    __syncthreads();
}

__device__ __forceinline__ float inv_cdf_one(const float* c, float tk) {
    // searchsorted left: first j with c[j] >= tk.
    // Range [0,512] has size 513 -> needs exactly 10 halvings.
    int l = 0, h = AA;
    #pragma unroll
    for (int it = 0; it < 10; ++it) {
        if (l < h) {
            int m = (l + h) >> 1;
            if (c[m] < tk) l = m + 1; else h = m;
        }
    }
    int j = min(l, AA - 1);
    float cp = (j > 0) ? c[j - 1] : 0.f;
    float dens = c[j] - cp;
    float p = (float)j + (tk - cp) / fmaxf(dens, 1e-6f);
    return 2.f * p / (float)AA - 1.f;
}

__global__ void __launch_bounds__(512) prep_kernel(const float* __restrict__ attx,
                                                   const float* __restrict__ atty) {
    __shared__ float sbuf[64];
    __shared__ float cx[AA];
    __shared__ float cy[AA];
    int n = blockIdx.x;
    int t = threadIdx.x;

    float ax = attx[n * AA + t];
    float ay = atty[n * AA + t];

    float sax, say;
    blockSum2(ax, ay, sbuf, &sax, &say);
    ax = ax / sax * (float)OUTS;
    ay = ay / say * (float)OUTS;

    const float thr0 = 4.0f * (float)OUTS / (float)AA;  // DENSE*out/A
    #pragma unroll
    for (int it = 0; it < 5; ++it) {
        float mx, my;
        blockMax2(ax, ay, sbuf, &mx, &my);
        float tt = fminf(mx, my);
        if (it == 0) tt = fminf(tt, thr0);
        ax = fminf(ax, tt);
        ay = fminf(ay, tt);
        blockSum2(ax, ay, sbuf, &sax, &say);
        ax += ((float)OUTS - sax) / (float)AA;
        ay += ((float)OUTS - say) / (float)AA;
    }

    blockScan2(ax, ay, cx, cy, sbuf);

    float stepx = cx[AA - 1] / (float)OUTS;
    float stepy = cy[AA - 1] / (float)OUTS;
    float tkx = ((float)t + 0.5f) * stepx;
    float tky = ((float)t + 0.5f) * stepy;

    g_px[n * OUTS + t] = inv_cdf_one(cx, tkx);
    g_py[n * OUTS + t] = inv_cdf_one(cy, tky);
}

// Pair-mapped direct-gather sampler.
// Thread (tx,ty) of block (bx,n) handles row i = bx*2+ty, pixels
// {2tx, 2tx+1, 2tx+256, 2tx+257}. Adjacent-x corners fetched as one aligned
// LDG.64 + predicated scalar fixup for odd x0. Stores: STG.64 (sampled) and
// STG.128 (grid). All gathers issued before any consumption (MLP ~36).
__global__ void __launch_bounds__(256) sample_kernel(const float* __restrict__ data,
                                                     float* __restrict__ out_s,
                                                     float4* __restrict__ out_g) {
    int tx = threadIdx.x;                 // 0..127
    int i = blockIdx.x * 2 + threadIdx.y; // output row
    int n = blockIdx.y;

    float py = __ldg(&g_py[n * OUTS + i]);
    float iy = (py + 1.f) * 0.5f * (float)(HH - 1);
    float fy = floorf(iy);
    float wy = iy - fy;
    int y0 = min(max((int)fy, 0), HH - 1);
    int y1 = min(y0 + 1, HH - 1);
    float omwy = 1.f - wy;

    float2 pxp0 = __ldg((const float2*)&g_px[n * OUTS + 2 * tx]);
    float2 pxp1 = __ldg((const float2*)&g_px[n * OUTS + 2 * tx + 256]);
    float pxv[4] = {pxp0.x, pxp0.y, pxp1.x, pxp1.y};

    int xb[4];
    bool odd[4], needx[4];
    int xn[4];
    float wx[4];
    #pragma unroll
    for (int q = 0; q < 4; ++q) {
        float ix = (pxv[q] + 1.f) * 0.5f * (float)(WW - 1);
        float fx = floorf(ix);
        wx[q] = ix - fx;
        int x0 = min(max((int)fx, 0), WW - 1);
        xb[q] = x0 & ~1;
        odd[q] = (x0 & 1);
        needx[q] = odd[q] && (x0 < WW - 1);
        xn[q] = x0 + 1;
    }

    const float* img = data + (size_t)n * CC * HH * WW;
    const float* rp[2];
    rp[0] = img + (size_t)y0 * WW;
    rp[1] = img + (size_t)y1 * WW;

    // batch-issue all gathers
    float2 f[2][CC][4];
    float ext[2][CC][4];
    #pragma unroll
    for (int c = 0; c < CC; ++c) {
        #pragma unroll
        for (int r = 0; r < 2; ++r) {
            const float* row = rp[r] + (size_t)c * HH * WW;
            #pragma unroll
            for (int q = 0; q < 4; ++q)
                f[r][c][q] = __ldg((const float2*)(row + xb[q]));
        }
    }
    #pragma unroll
    for (int c = 0; c < CC; ++c) {
        #pragma unroll
        for (int r = 0; r < 2; ++r) {
            const float* row = rp[r] + (size_t)c * HH * WW;
            #pragma unroll
            for (int q = 0; q < 4; ++q) {
                float e = 0.f;
                if (needx[q]) e = __ldg(row + xn[q]);
                ext[r][c][q] = e;
            }
        }
    }

    // combine + store
    #pragma unroll
    for (int c = 0; c < CC; ++c) {
        float res[4];
        #pragma unroll
        for (int q = 0; q < 4; ++q) {
            float v00 = odd[q] ? f[0][c][q].y : f[0][c][q].x;
            float v01 = needx[q] ? ext[0][c][q] : f[0][c][q].y;
            float v10 = odd[q] ? f[1][c][q].y : f[1][c][q].x;
            float v11 = needx[q] ? ext[1][c][q] : f[1][c][q].y;
            float omwx = 1.f - wx[q];
            float top = v00 * omwx + v01 * wx[q];
            float bot = v10 * omwx + v11 * wx[q];
            res[q] = top * omwy + bot * wy;
        }
        float* o = out_s + (((size_t)n * CC + c) * HH + i) * WW;
        *(float2*)(o + 2 * tx)       = make_float2(res[0], res[1]);
        *(float2*)(o + 2 * tx + 256) = make_float2(res[2], res[3]);
    }

    size_t gb = ((size_t)n * OUTS + i) * (OUTS / 2) + tx;  // float4 units
    out_g[gb]       = make_float4(pxv[0], py, pxv[1], py);
    out_g[gb + 128] = make_float4(pxv[2], py, pxv[3], py);
}

extern "C" void kernel_launch(void* const* d_in, const int* in_sizes, int n_in,
                              void* d_out, int out_size) {
    const float* data = (const float*)d_in[0];
    const float* attx = (const float*)d_in[1];
    const float* atty = (const float*)d_in[2];

    int N = in_sizes[1] / AA;   // attx is (N, 512, 1)

    float* out = (float*)d_out;
    float* out_s = out;                                        // (N, C, 512, 512)
    float4* out_g = (float4*)(out + (size_t)N * CC * HH * WW); // (N, 512, 512, 2)

    prep_kernel<<<N, 512>>>(attx, atty);
    dim3 block(128, 2);
    dim3 grid(OUTS / 2, N);
    sample_kernel<<<grid, block>>>(data, out_s, out_g);
}